// round 15
// baseline (speedup 1.0000x reference)
#include <cuda_runtime.h>
#include <cuda_bf16.h>

#define FULL_MASK 0xffffffffu

__global__ __launch_bounds__(128, 6) void anfis_kernel(
    const float* __restrict__ x,
    const float* __restrict__ mu,
    const float* __restrict__ sg,
    const float* __restrict__ ta,
    const float* __restrict__ tb,
    const float* __restrict__ tc,
    const float* __restrict__ td,
    const float* __restrict__ mfmix,
    const float* __restrict__ tnw,
    const float* __restrict__ conseq,
    const int*   __restrict__ ridx,
    float* __restrict__ out0,   // [B]
    float* __restrict__ outN,   // [B,128]
    float* __restrict__ outM,   // [B,14]
    int B)
{
    // Coefficients in SMEM: sC[k][c][l15] = float4 chunk c of rule r = 8*l15 + k.
    // Lanes l and l+16 read the same address (broadcast); lanes 0..15 stride 16B.
    __shared__ float4 sC[8][2][16];

    const int tid    = blockIdx.x * blockDim.x + threadIdx.x;
    const int warp   = tid >> 5;
    const int lane   = tid & 31;
    const int nwarps = (gridDim.x * blockDim.x) >> 5;
    const int step   = 2 * nwarps;
    const int l15    = lane & 15;   // rule group within half
    const int half   = lane >> 4;   // 0 = element A, 1 = element B

    // ---- one-time smem fill: 256 float4 entries, 128 threads x2 ----
    for (int i = threadIdx.x; i < 256; i += 128) {
        const int k = i >> 5;
        const int c = (i >> 4) & 1;
        const int l = i & 15;
        const int r = 8 * l + k;
        sC[k][c][l] = reinterpret_cast<const float4*>(conseq)[r * 2 + c];
    }

    // ---- structure check: ridx[r][f] must equal bit (6-f) of r ----
    bool ok = true;
#pragma unroll
    for (int k = 0; k < 8; ++k) {
        const int r = 8 * l15 + k;
        int m = 0;
#pragma unroll
        for (int f = 0; f < 7; ++f) m |= (ridx[r * 7 + f] & 1) << f;
        const int em = ((l15 >> 3) & 1)
                     | (((l15 >> 2) & 1) << 1)
                     | (((l15 >> 1) & 1) << 2)
                     | ((l15 & 1) << 3)
                     | (((k >> 2) & 1) << 4)
                     | (((k >> 1) & 1) << 5)
                     | ((k & 1) << 6);
        ok = ok && (m == em);
    }
    const bool fast = __all_sync(FULL_MASK, ok) && ((B & 1) == 0);

    // Gather sources for the 4 lane-fixed features (element offset ebase)
    const int ebase = half * 14;
    const int src0 = ebase + 0 + ((l15 >> 3) & 1);
    const int src1 = ebase + 2 + ((l15 >> 2) & 1);
    const int src2 = ebase + 4 + ((l15 >> 1) & 1);
    const int src3 = ebase + 6 + (l15 & 1);

    const float alpha = 1.f / (1.f + __expf(-mfmix[0]));
    const float w     = 1.f / (1.f + __expf(-tnw[0]));

    // ---- element-invariant membership params (lanes 0..27: j=lane%14) ----
    const int j = (lane < 14) ? lane : (lane < 28 ? lane - 14 : 0);
    float muv, i2s, av, bv, cv, dv, iba, idc;
    {
        muv = mu[j];
        float s = fmaxf(sg[j], 1e-6f);
        i2s = 1.f / (2.f * s * s);
        float p0 = ta[j], p1 = tb[j], p2 = tc[j], p3 = td[j];
        float t;
        t = fminf(p0, p1); p1 = fmaxf(p0, p1); p0 = t;
        t = fminf(p2, p3); p3 = fmaxf(p2, p3); p2 = t;
        t = fminf(p0, p2); p2 = fmaxf(p0, p2); p0 = t;
        t = fminf(p1, p3); p3 = fmaxf(p1, p3); p1 = t;
        t = fminf(p1, p2); p2 = fmaxf(p1, p2); p1 = t;
        av = p0; bv = p1; cv = p2; dv = p3;
        iba = 1.f / (p1 - p0 + 1e-6f);
        idc = 1.f / (p3 - p2 + 1e-6f);
    }

    __syncthreads();   // sC ready

    if (fast) {
        // ---- half-warp split dual-element loop (B even) with prefetched x ----
        int b0 = 2 * warp;
        float xf = 0.f;
        if (b0 < B && lane < 28)
            xf = __ldg(x + b0 * 7 + (lane >> 1));

        for (; b0 < B; b0 += step) {
            // prefetch next iteration's membership input
            float xf_next = 0.f;
            {
                const int bn = b0 + step;
                if (bn < B && lane < 28)
                    xf_next = __ldg(x + bn * 7 + (lane >> 1));
            }

            // this half's x row (2 distinct uniform addresses per warp)
            const float* xe = x + (b0 + half) * 7;
            float xv0 = __ldg(xe+0), xv1 = __ldg(xe+1), xv2 = __ldg(xe+2),
                  xv3 = __ldg(xe+3), xv4 = __ldg(xe+4), xv5 = __ldg(xe+5),
                  xv6 = __ldg(xe+6);

            // ---- memberships for both elements across lanes 0..27 ----
            float memv = 0.f;
            if (lane < 28) {
                float t     = xf - muv;
                float gauss = __expf(-t * t * i2s);
                float left  = fminf(fmaxf((xf - av) * iba, 0.f), 1.f);
                float right = fminf(fmaxf((dv - xf) * idc, 0.f), 1.f);
                float flat  = (xf >= bv && xf <= cv) ? 1.f : 0.f;
                float trap  = fmaxf(fminf(left, right), flat);
                memv = trap + alpha * (gauss - trap);
                __stcs(outM + b0 * 14 + lane, memv);
            }

            // ---- 10 gathers serve BOTH elements (per-half sources) ----
            float g0 = __shfl_sync(FULL_MASK, memv, src0);
            float g1 = __shfl_sync(FULL_MASK, memv, src1);
            float g2 = __shfl_sync(FULL_MASK, memv, src2);
            float g3 = __shfl_sync(FULL_MASK, memv, src3);
            float A4 = __shfl_sync(FULL_MASK, memv, ebase + 8);
            float B4 = __shfl_sync(FULL_MASK, memv, ebase + 9);
            float A5 = __shfl_sync(FULL_MASK, memv, ebase + 10);
            float B5 = __shfl_sync(FULL_MASK, memv, ebase + 11);
            float A6 = __shfl_sync(FULL_MASK, memv, ebase + 12);
            float B6 = __shfl_sync(FULL_MASK, memv, ebase + 13);

            float pp = (g0 * g1) * (g2 * g3);
            float pm = fminf(fminf(g0, g1), fminf(g2, g3));

            // ---- 8 rules per lane: r = 8*l15 + k; k bits = features 4,5,6 ----
            float fir[8];
            float s1 = 0.f, s2 = 0.f;
#pragma unroll
            for (int k = 0; k < 8; ++k) {
                const float4 c0 = sC[k][0][l15];
                const float4 c1 = sC[k][1][l15];

                float u = (k & 4) ? B4 : A4;   // feature 4
                float v = (k & 2) ? B5 : A5;   // feature 5
                float t = (k & 1) ? B6 : A6;   // feature 6

                float p  = pp * ((u * v) * t);
                float mn = fminf(pm, fminf(u, fminf(v, t)));
                float fk = mn + w * (p - mn);
                fir[k] = fk;

                float ro = c0.x;
                ro = fmaf(c0.y, xv0, ro);
                ro = fmaf(c0.z, xv1, ro);
                ro = fmaf(c0.w, xv2, ro);
                ro = fmaf(c1.x, xv3, ro);
                ro = fmaf(c1.y, xv4, ro);
                ro = fmaf(c1.z, xv5, ro);
                ro = fmaf(c1.w, xv6, ro);

                s1 += fk;
                s2 = fmaf(fk, ro, s2);
            }

            // ---- 4-stage reduction within each 16-lane half (A,B concurrent) ----
#pragma unroll
            for (int off = 8; off > 0; off >>= 1) {
                s1 += __shfl_xor_sync(FULL_MASK, s1, off);
                s2 += __shfl_xor_sync(FULL_MASK, s2, off);
            }
            const float inv = __fdividef(1.f, s1 + 1e-8f);

            float4 n0 = make_float4(fir[0]*inv, fir[1]*inv, fir[2]*inv, fir[3]*inv);
            float4 n1 = make_float4(fir[4]*inv, fir[5]*inv, fir[6]*inv, fir[7]*inv);
            float* nb = outN + (b0 + half) * 128 + 8 * l15;
            __stcs(reinterpret_cast<float4*>(nb),     n0);
            __stcs(reinterpret_cast<float4*>(nb) + 1, n1);
            if (l15 == 0)
                __stcs(out0 + b0 + half, s2 * inv);

            xf = xf_next;
        }
    } else {
        // ---- generic fallback (structure violated or odd B): 1 element/iter ----
        // Coefficients read straight from gmem (perf irrelevant here).
        int mask[4];
#pragma unroll
        for (int k = 0; k < 4; ++k) {
            const int r = 4 * lane + k;
            int m = 0;
#pragma unroll
            for (int f = 0; f < 7; ++f) m |= (ridx[r * 7 + f] & 1) << f;
            mask[k] = m;
        }
        const float4* cp4 = reinterpret_cast<const float4*>(conseq + (4 * lane) * 8);

        for (int b = warp; b < B; b += nwarps) {
            const float* xb = x + b * 7;
            float xv0 = __ldg(xb+0), xv1 = __ldg(xb+1), xv2 = __ldg(xb+2),
                  xv3 = __ldg(xb+3), xv4 = __ldg(xb+4), xv5 = __ldg(xb+5),
                  xv6 = __ldg(xb+6);
            float memv = 0.f;
            if (lane < 14) {
                float xfv = __ldg(xb + (lane >> 1));
                float t     = xfv - muv;
                float gauss = __expf(-t * t * i2s);
                float left  = fminf(fmaxf((xfv - av) * iba, 0.f), 1.f);
                float right = fminf(fmaxf((dv - xfv) * idc, 0.f), 1.f);
                float flat  = (xfv >= bv && xfv <= cv) ? 1.f : 0.f;
                float trap  = fmaxf(fminf(left, right), flat);
                memv = trap + alpha * (gauss - trap);
                outM[b * 14 + lane] = memv;
            }
            float mA[7], mB[7];
#pragma unroll
            for (int f = 0; f < 7; ++f) {
                mA[f] = __shfl_sync(FULL_MASK, memv, 2 * f);
                mB[f] = __shfl_sync(FULL_MASK, memv, 2 * f + 1);
            }
            float fir[4], s1 = 0.f, s2 = 0.f;
#pragma unroll
            for (int k = 0; k < 4; ++k) {
                const int m = mask[k];
                const float4 c0 = __ldg(&cp4[2 * k]);
                const float4 c1 = __ldg(&cp4[2 * k + 1]);
                float p = 1.f, mn = 2.f;
#pragma unroll
                for (int f = 0; f < 7; ++f) {
                    float g = (m & (1 << f)) ? mB[f] : mA[f];
                    p *= g; mn = fminf(mn, g);
                }
                float fk = mn + w * (p - mn);
                fir[k] = fk;
                float ro = c0.x;
                ro = fmaf(c0.y, xv0, ro);
                ro = fmaf(c0.z, xv1, ro);
                ro = fmaf(c0.w, xv2, ro);
                ro = fmaf(c1.x, xv3, ro);
                ro = fmaf(c1.y, xv4, ro);
                ro = fmaf(c1.z, xv5, ro);
                ro = fmaf(c1.w, xv6, ro);
                s1 += fk;
                s2 = fmaf(fk, ro, s2);
            }
#pragma unroll
            for (int off = 16; off > 0; off >>= 1) {
                s1 += __shfl_xor_sync(FULL_MASK, s1, off);
                s2 += __shfl_xor_sync(FULL_MASK, s2, off);
            }
            const float inv = __fdividef(1.f, s1 + 1e-8f);
            float4 nf = make_float4(fir[0]*inv, fir[1]*inv, fir[2]*inv, fir[3]*inv);
            reinterpret_cast<float4*>(outN + b * 128)[lane] = nf;
            if (lane == 0) out0[b] = s2 * inv;
        }
    }
}

extern "C" void kernel_launch(void* const* d_in, const int* in_sizes, int n_in,
                              void* d_out, int out_size) {
    const float* x      = (const float*)d_in[0];
    const float* mu     = (const float*)d_in[1];
    const float* sg     = (const float*)d_in[2];
    const float* ta     = (const float*)d_in[3];
    const float* tb     = (const float*)d_in[4];
    const float* tc     = (const float*)d_in[5];
    const float* td     = (const float*)d_in[6];
    const float* mfmix  = (const float*)d_in[7];
    const float* tnw    = (const float*)d_in[8];
    const float* conseq = (const float*)d_in[9];
    const int*   ridx   = (const int*)d_in[10];

    const int B = in_sizes[0] / 7;

    float* o  = (float*)d_out;
    float* oN = o + B;                // norm_firing [B,128]
    float* oM = o + B + B * 128;      // mem [B,14]

    // Single wave: 148 SMs x 6 blocks/SM, 128 threads (24 warps/SM),
    // 2 elements per warp-iteration (half-warp per element).
    anfis_kernel<<<888, 128>>>(x, mu, sg, ta, tb, tc, td, mfmix, tnw,
                               conseq, ridx, o, oN, oM, B);
}

// round 16
// speedup vs baseline: 1.1566x; 1.1566x over previous
#include <cuda_runtime.h>
#include <cuda_bf16.h>

#define FULL_MASK 0xffffffffu

__global__ __launch_bounds__(128, 6) void anfis_kernel(
    const float* __restrict__ x,
    const float* __restrict__ mu,
    const float* __restrict__ sg,
    const float* __restrict__ ta,
    const float* __restrict__ tb,
    const float* __restrict__ tc,
    const float* __restrict__ td,
    const float* __restrict__ mfmix,
    const float* __restrict__ tnw,
    const float* __restrict__ conseq,
    const int*   __restrict__ ridx,
    float* __restrict__ out0,   // [B]
    float* __restrict__ outN,   // [B,128]
    float* __restrict__ outM,   // [B,14]
    int B)
{
    // Coefficient table in SMEM, conflict-free layout:
    // sC[k][c][lane] holds float4 chunk c of rule r = 4*lane + k.
    __shared__ float4 sC[4][2][32];

    const int tid    = blockIdx.x * blockDim.x + threadIdx.x;
    const int warp   = tid >> 5;
    const int lane   = tid & 31;
    const int nwarps = (gridDim.x * blockDim.x) >> 5;
    const int step   = 2 * nwarps;

    // ---- one-time setup: copy this block's coefficient table (128 threads) ----
    {
        const int k = threadIdx.x >> 5;       // 0..3
        const int l = threadIdx.x & 31;       // 0..31
        const int r = 4 * l + k;
        const float4* cp = reinterpret_cast<const float4*>(conseq + r * 8);
        sC[k][0][l] = cp[0];
        sC[k][1][l] = cp[1];
    }

    // ---- per-lane rule masks (setup only; dead in fast loop) ----
    int mask[4];
#pragma unroll
    for (int k = 0; k < 4; ++k) {
        const int r = 4 * lane + k;
        int m = 0;
#pragma unroll
        for (int f = 0; f < 7; ++f) m |= (ridx[r * 7 + f] & 1) << f;
        mask[k] = m;
    }

    // Structure check:
    //  (a) masks agree on features 0..4 across k,
    //  (b) feature5 set-bit == bit1(k), feature6 set-bit == bit0(k).
    const int diff = (mask[0]^mask[1]) | (mask[0]^mask[2]) | (mask[0]^mask[3]);
    bool ok = (diff & 0x1F) == 0;
#pragma unroll
    for (int k = 0; k < 4; ++k)
        ok = ok && (((mask[k] >> 5) & 1) == ((k >> 1) & 1))
                && (((mask[k] >> 6) & 1) == (k & 1));
    // Fast path additionally requires even B (branch-free dual-element loop).
    const bool fast = __all_sync(FULL_MASK, ok) && ((B & 1) == 0);

    // Gather source lanes for the 5 lane-fixed features (mem index = 2f + set)
    const int src0 = 0 + ((mask[0] >> 0) & 1);
    const int src1 = 2 + ((mask[0] >> 1) & 1);
    const int src2 = 4 + ((mask[0] >> 2) & 1);
    const int src3 = 6 + ((mask[0] >> 3) & 1);
    const int src4 = 8 + ((mask[0] >> 4) & 1);

    const float alpha = 1.f / (1.f + __expf(-mfmix[0]));
    const float w     = 1.f / (1.f + __expf(-tnw[0]));

    // ---- element-invariant membership params (lanes 0..27: j=lane%14) ----
    const int j = (lane < 14) ? lane : (lane < 28 ? lane - 14 : 0);
    float muv, i2s, av, bv, cv, dv, iba, idc;
    {
        muv = mu[j];
        float s = fmaxf(sg[j], 1e-6f);
        i2s = 1.f / (2.f * s * s);
        float p0 = ta[j], p1 = tb[j], p2 = tc[j], p3 = td[j];
        float t;
        t = fminf(p0, p1); p1 = fmaxf(p0, p1); p0 = t;
        t = fminf(p2, p3); p3 = fmaxf(p2, p3); p2 = t;
        t = fminf(p0, p2); p2 = fmaxf(p0, p2); p0 = t;
        t = fminf(p1, p3); p3 = fmaxf(p1, p3); p1 = t;
        t = fminf(p1, p2); p2 = fmaxf(p1, p2); p1 = t;
        av = p0; bv = p1; cv = p2; dv = p3;
        iba = 1.f / (p1 - p0 + 1e-6f);
        idc = 1.f / (p3 - p2 + 1e-6f);
    }

    __syncthreads();   // sC ready

    if (fast) {
        // ---- dual-element loop (B even), membership pipelined one iter ahead ----
        int b0 = 2 * warp;

        // Preheader: membership + outM store for the first iteration.
        float memv = 0.f;
        if (b0 < B && lane < 28) {
            float xf = __ldg(x + b0 * 7 + (lane >> 1));  // lane = 14e + 2f + set
            float t     = xf - muv;
            float gauss = __expf(-t * t * i2s);
            float left  = fminf(fmaxf((xf - av) * iba, 0.f), 1.f);
            float right = fminf(fmaxf((dv - xf) * idc, 0.f), 1.f);
            float flat  = (xf >= bv && xf <= cv) ? 1.f : 0.f;
            float trap  = fmaxf(fminf(left, right), flat);
            memv = trap + alpha * (gauss - trap);
            __stcs(outM + b0 * 14 + lane, memv);
        }

        for (; b0 < B; b0 += step) {
            // x + b0*7 is 8B-aligned (b0 even): 7 uniform LDG.64 cover 14 floats
            const float2* xb2 = reinterpret_cast<const float2*>(x + b0 * 7);

            // prefetch next iteration's membership input
            const int bn = b0 + step;
            const bool pn = (bn < B) && (lane < 28);
            float xf_next = 0.f;
            if (pn) xf_next = __ldg(x + bn * 7 + (lane >> 1));

            // vectorized uniform x broadcasts (7 LDG.64)
            float2 p01 = __ldg(xb2 + 0);
            float2 p23 = __ldg(xb2 + 1);
            float2 p45 = __ldg(xb2 + 2);
            float2 p67 = __ldg(xb2 + 3);
            float2 p89 = __ldg(xb2 + 4);
            float2 pAB = __ldg(xb2 + 5);
            float2 pCD = __ldg(xb2 + 6);
            float ax0 = p01.x, ax1 = p01.y, ax2 = p23.x, ax3 = p23.y,
                  ax4 = p45.x, ax5 = p45.y, ax6 = p67.x;
            float bx0 = p67.y, bx1 = p89.x, bx2 = p89.y, bx3 = pAB.x,
                  bx4 = pAB.y, bx5 = pCD.x, bx6 = pCD.y;

            // ---- gathers: element A (lanes 0..13), element B (+14) ----
            float a_g0 = __shfl_sync(FULL_MASK, memv, src0);
            float b_g0 = __shfl_sync(FULL_MASK, memv, src0 + 14);
            float a_g1 = __shfl_sync(FULL_MASK, memv, src1);
            float b_g1 = __shfl_sync(FULL_MASK, memv, src1 + 14);
            float a_g2 = __shfl_sync(FULL_MASK, memv, src2);
            float b_g2 = __shfl_sync(FULL_MASK, memv, src2 + 14);
            float a_g3 = __shfl_sync(FULL_MASK, memv, src3);
            float b_g3 = __shfl_sync(FULL_MASK, memv, src3 + 14);
            float a_g4 = __shfl_sync(FULL_MASK, memv, src4);
            float b_g4 = __shfl_sync(FULL_MASK, memv, src4 + 14);
            // pair features 5 (lanes 10/11) and 6 (lanes 12/13)
            float aA5 = __shfl_sync(FULL_MASK, memv, 10);
            float aB5 = __shfl_sync(FULL_MASK, memv, 11);
            float aA6 = __shfl_sync(FULL_MASK, memv, 12);
            float aB6 = __shfl_sync(FULL_MASK, memv, 13);
            float bA5 = __shfl_sync(FULL_MASK, memv, 24);
            float bB5 = __shfl_sync(FULL_MASK, memv, 25);
            float bA6 = __shfl_sync(FULL_MASK, memv, 26);
            float bB6 = __shfl_sync(FULL_MASK, memv, 27);

            float a_pp = ((a_g0 * a_g1) * (a_g2 * a_g3)) * a_g4;
            float a_pm = fminf(fminf(fminf(a_g0, a_g1), fminf(a_g2, a_g3)), a_g4);
            float b_pp = ((b_g0 * b_g1) * (b_g2 * b_g3)) * b_g4;
            float b_pm = fminf(fminf(fminf(b_g0, b_g1), fminf(b_g2, b_g3)), b_g4);

            float firA[4], firB[4];
            float s1a = 0.f, s2a = 0.f, s1b = 0.f, s2b = 0.f;
#pragma unroll
            for (int k = 0; k < 4; ++k) {
                // coefficients from SMEM: conflict-free LDS.128
                const float4 c0 = sC[k][0][lane];
                const float4 c1 = sC[k][1][lane];

                // compile-time feature-5/6 selection: f5 = bit1(k), f6 = bit0(k)
                float u  = (k & 2) ? aB5 : aA5;
                float v  = (k & 1) ? aB6 : aA6;
                float u2 = (k & 2) ? bB5 : bA5;
                float v2 = (k & 1) ? bB6 : bA6;

                float p   = a_pp * (u * v);
                float mn  = fminf(a_pm, fminf(u, v));
                float fA  = mn + w * (p - mn);
                firA[k] = fA;
                float p2  = b_pp * (u2 * v2);
                float mn2 = fminf(b_pm, fminf(u2, v2));
                float fB  = mn2 + w * (p2 - mn2);
                firB[k] = fB;

                float roA = c0.x;
                roA = fmaf(c0.y, ax0, roA);
                roA = fmaf(c0.z, ax1, roA);
                roA = fmaf(c0.w, ax2, roA);
                roA = fmaf(c1.x, ax3, roA);
                roA = fmaf(c1.y, ax4, roA);
                roA = fmaf(c1.z, ax5, roA);
                roA = fmaf(c1.w, ax6, roA);
                float roB = c0.x;
                roB = fmaf(c0.y, bx0, roB);
                roB = fmaf(c0.z, bx1, roB);
                roB = fmaf(c0.w, bx2, roB);
                roB = fmaf(c1.x, bx3, roB);
                roB = fmaf(c1.y, bx4, roB);
                roB = fmaf(c1.z, bx5, roB);
                roB = fmaf(c1.w, bx6, roB);

                s1a += fA; s2a = fmaf(fA, roA, s2a);
                s1b += fB; s2b = fmaf(fB, roB, s2b);
            }

            // ---- next iteration's membership, in the same basic block as the
            // butterfly: ptxas interleaves this independent ALU/MUFU work into
            // the SHFL stall shadows below ----
            float memv_next = 0.f;
            if (pn) {
                float t     = xf_next - muv;
                float gauss = __expf(-t * t * i2s);
                float left  = fminf(fmaxf((xf_next - av) * iba, 0.f), 1.f);
                float right = fminf(fmaxf((dv - xf_next) * idc, 0.f), 1.f);
                float flat  = (xf_next >= bv && xf_next <= cv) ? 1.f : 0.f;
                float trap  = fmaxf(fminf(left, right), flat);
                memv_next = trap + alpha * (gauss - trap);
                __stcs(outM + bn * 14 + lane, memv_next);
            }

            // ---- 4 interleaved butterfly reduction chains ----
#pragma unroll
            for (int off = 16; off > 0; off >>= 1) {
                s1a += __shfl_xor_sync(FULL_MASK, s1a, off);
                s1b += __shfl_xor_sync(FULL_MASK, s1b, off);
                s2a += __shfl_xor_sync(FULL_MASK, s2a, off);
                s2b += __shfl_xor_sync(FULL_MASK, s2b, off);
            }
            const float invA = __fdividef(1.f, s1a + 1e-8f);
            const float invB = __fdividef(1.f, s1b + 1e-8f);

            float4 nfA = make_float4(firA[0]*invA, firA[1]*invA, firA[2]*invA, firA[3]*invA);
            float4 nfB = make_float4(firB[0]*invB, firB[1]*invB, firB[2]*invB, firB[3]*invB);
            __stcs(reinterpret_cast<float4*>(outN + b0 * 128) + lane, nfA);
            __stcs(reinterpret_cast<float4*>(outN + (b0 + 1) * 128) + lane, nfB);
            if (lane == 0) {
                // out0 + b0 is 8B-aligned (b0 even): one packed STG.64
                float2 o2 = make_float2(s2a * invA, s2b * invB);
                __stcs(reinterpret_cast<float2*>(out0 + b0), o2);
            }

            memv = memv_next;
        }
    } else {
        // ---- generic fallback (structure violated or odd B): 1 element/iter ----
        for (int b = warp; b < B; b += nwarps) {
            const float* xb = x + b * 7;
            float xv0 = __ldg(xb+0), xv1 = __ldg(xb+1), xv2 = __ldg(xb+2),
                  xv3 = __ldg(xb+3), xv4 = __ldg(xb+4), xv5 = __ldg(xb+5),
                  xv6 = __ldg(xb+6);
            float memv = 0.f;
            if (lane < 14) {
                float xfv = __ldg(xb + (lane >> 1));
                float t     = xfv - muv;
                float gauss = __expf(-t * t * i2s);
                float left  = fminf(fmaxf((xfv - av) * iba, 0.f), 1.f);
                float right = fminf(fmaxf((dv - xfv) * idc, 0.f), 1.f);
                float flat  = (xfv >= bv && xfv <= cv) ? 1.f : 0.f;
                float trap  = fmaxf(fminf(left, right), flat);
                memv = trap + alpha * (gauss - trap);
                outM[b * 14 + lane] = memv;
            }
            float mA[7], mB[7];
#pragma unroll
            for (int f = 0; f < 7; ++f) {
                mA[f] = __shfl_sync(FULL_MASK, memv, 2 * f);
                mB[f] = __shfl_sync(FULL_MASK, memv, 2 * f + 1);
            }
            float fir[4], s1 = 0.f, s2 = 0.f;
#pragma unroll
            for (int k = 0; k < 4; ++k) {
                const int m = mask[k];
                const float4 c0 = sC[k][0][lane];
                const float4 c1 = sC[k][1][lane];
                float p = 1.f, mn = 2.f;
#pragma unroll
                for (int f = 0; f < 7; ++f) {
                    float g = (m & (1 << f)) ? mB[f] : mA[f];
                    p *= g; mn = fminf(mn, g);
                }
                float fk = mn + w * (p - mn);
                fir[k] = fk;
                float ro = c0.x;
                ro = fmaf(c0.y, xv0, ro);
                ro = fmaf(c0.z, xv1, ro);
                ro = fmaf(c0.w, xv2, ro);
                ro = fmaf(c1.x, xv3, ro);
                ro = fmaf(c1.y, xv4, ro);
                ro = fmaf(c1.z, xv5, ro);
                ro = fmaf(c1.w, xv6, ro);
                s1 += fk;
                s2 = fmaf(fk, ro, s2);
            }
#pragma unroll
            for (int off = 16; off > 0; off >>= 1) {
                s1 += __shfl_xor_sync(FULL_MASK, s1, off);
                s2 += __shfl_xor_sync(FULL_MASK, s2, off);
            }
            const float inv = __fdividef(1.f, s1 + 1e-8f);
            float4 nf = make_float4(fir[0]*inv, fir[1]*inv, fir[2]*inv, fir[3]*inv);
            reinterpret_cast<float4*>(outN + b * 128)[lane] = nf;
            if (lane == 0) out0[b] = s2 * inv;
        }
    }
}

extern "C" void kernel_launch(void* const* d_in, const int* in_sizes, int n_in,
                              void* d_out, int out_size) {
    const float* x      = (const float*)d_in[0];
    const float* mu     = (const float*)d_in[1];
    const float* sg     = (const float*)d_in[2];
    const float* ta     = (const float*)d_in[3];
    const float* tb     = (const float*)d_in[4];
    const float* tc     = (const float*)d_in[5];
    const float* td     = (const float*)d_in[6];
    const float* mfmix  = (const float*)d_in[7];
    const float* tnw    = (const float*)d_in[8];
    const float* conseq = (const float*)d_in[9];
    const int*   ridx   = (const int*)d_in[10];

    const int B = in_sizes[0] / 7;

    float* o  = (float*)d_out;
    float* oN = o + B;                // norm_firing [B,128]
    float* oM = o + B + B * 128;      // mem [B,14]

    // Single wave: 148 SMs x 6 blocks/SM, 128 threads (24 warps/SM), 2 elem/warp-iter
    anfis_kernel<<<888, 128>>>(x, mu, sg, ta, tb, tc, td, mfmix, tnw,
                               conseq, ridx, o, oN, oM, B);
}

// round 17
// speedup vs baseline: 1.1743x; 1.0153x over previous
#include <cuda_runtime.h>
#include <cuda_bf16.h>

#define FULL_MASK 0xffffffffu

__global__ __launch_bounds__(128, 7) void anfis_kernel(
    const float* __restrict__ x,
    const float* __restrict__ mu,
    const float* __restrict__ sg,
    const float* __restrict__ ta,
    const float* __restrict__ tb,
    const float* __restrict__ tc,
    const float* __restrict__ td,
    const float* __restrict__ mfmix,
    const float* __restrict__ tnw,
    const float* __restrict__ conseq,
    const int*   __restrict__ ridx,
    float* __restrict__ out0,   // [B]
    float* __restrict__ outN,   // [B,128]
    float* __restrict__ outM,   // [B,14]
    int B)
{
    // Coefficient table in SMEM, conflict-free layout:
    // sC[k][c][lane] holds float4 chunk c of rule r = 4*lane + k.
    __shared__ float4 sC[4][2][32];

    const int tid    = blockIdx.x * blockDim.x + threadIdx.x;
    const int warp   = tid >> 5;
    const int lane   = tid & 31;
    const int nwarps = (gridDim.x * blockDim.x) >> 5;
    const int step   = 2 * nwarps;

    // ---- one-time setup: copy this block's coefficient table (128 threads) ----
    {
        const int k = threadIdx.x >> 5;       // 0..3
        const int l = threadIdx.x & 31;       // 0..31
        const int r = 4 * l + k;
        const float4* cp = reinterpret_cast<const float4*>(conseq + r * 8);
        sC[k][0][l] = cp[0];
        sC[k][1][l] = cp[1];
    }

    // ---- per-lane rule masks (setup only; dead in fast loop) ----
    int mask[4];
#pragma unroll
    for (int k = 0; k < 4; ++k) {
        const int r = 4 * lane + k;
        int m = 0;
#pragma unroll
        for (int f = 0; f < 7; ++f) m |= (ridx[r * 7 + f] & 1) << f;
        mask[k] = m;
    }

    // Structure check:
    //  (a) masks agree on features 0..4 across k,
    //  (b) feature5 set-bit == bit1(k), feature6 set-bit == bit0(k).
    const int diff = (mask[0]^mask[1]) | (mask[0]^mask[2]) | (mask[0]^mask[3]);
    bool ok = (diff & 0x1F) == 0;
#pragma unroll
    for (int k = 0; k < 4; ++k)
        ok = ok && (((mask[k] >> 5) & 1) == ((k >> 1) & 1))
                && (((mask[k] >> 6) & 1) == (k & 1));
    // Fast path additionally requires even B (branch-free dual-element loop).
    const bool fast = __all_sync(FULL_MASK, ok) && ((B & 1) == 0);

    // Gather source lanes for the 5 lane-fixed features (mem index = 2f + set)
    const int src0 = 0 + ((mask[0] >> 0) & 1);
    const int src1 = 2 + ((mask[0] >> 1) & 1);
    const int src2 = 4 + ((mask[0] >> 2) & 1);
    const int src3 = 6 + ((mask[0] >> 3) & 1);
    const int src4 = 8 + ((mask[0] >> 4) & 1);

    const float alpha = 1.f / (1.f + __expf(-mfmix[0]));
    const float w     = 1.f / (1.f + __expf(-tnw[0]));

    // ---- element-invariant membership params (lanes 0..27: j=lane%14) ----
    const int j = (lane < 14) ? lane : (lane < 28 ? lane - 14 : 0);
    float muv, i2s, av, bv, cv, dv, iba, idc;
    {
        muv = mu[j];
        float s = fmaxf(sg[j], 1e-6f);
        i2s = 1.f / (2.f * s * s);
        float p0 = ta[j], p1 = tb[j], p2 = tc[j], p3 = td[j];
        float t;
        t = fminf(p0, p1); p1 = fmaxf(p0, p1); p0 = t;
        t = fminf(p2, p3); p3 = fmaxf(p2, p3); p2 = t;
        t = fminf(p0, p2); p2 = fmaxf(p0, p2); p0 = t;
        t = fminf(p1, p3); p3 = fmaxf(p1, p3); p1 = t;
        t = fminf(p1, p2); p2 = fmaxf(p1, p2); p1 = t;
        av = p0; bv = p1; cv = p2; dv = p3;
        iba = 1.f / (p1 - p0 + 1e-6f);
        idc = 1.f / (p3 - p2 + 1e-6f);
    }

    __syncthreads();   // sC ready

    if (fast) {
        // ---- branch-free dual-element loop (B even) with prefetched x ----
        int b0 = 2 * warp;
        float xf = 0.f;
        if (b0 < B && lane < 28)
            xf = __ldg(x + b0 * 7 + (lane >> 1));

        for (; b0 < B; b0 += step) {
            // x + b0*7 is 8B-aligned (b0 even): 7 uniform LDG.64 cover 14 floats
            const float2* xb2 = reinterpret_cast<const float2*>(x + b0 * 7);

            // prefetch next iteration's xf (latency hidden under this iteration)
            float xf_next = 0.f;
            {
                const int bn = b0 + step;
                if (bn < B && lane < 28)
                    xf_next = __ldg(x + bn * 7 + (lane >> 1));
            }

            // vectorized uniform x broadcasts (7 LDG.64 instead of 14 LDG.32)
            float2 p01 = __ldg(xb2 + 0);
            float2 p23 = __ldg(xb2 + 1);
            float2 p45 = __ldg(xb2 + 2);
            float2 p67 = __ldg(xb2 + 3);
            float2 p89 = __ldg(xb2 + 4);
            float2 pAB = __ldg(xb2 + 5);
            float2 pCD = __ldg(xb2 + 6);
            float ax0 = p01.x, ax1 = p01.y, ax2 = p23.x, ax3 = p23.y,
                  ax4 = p45.x, ax5 = p45.y, ax6 = p67.x;
            float bx0 = p67.y, bx1 = p89.x, bx2 = p89.y, bx3 = pAB.x,
                  bx4 = pAB.y, bx5 = pCD.x, bx6 = pCD.y;

            // ---- memberships for both elements across lanes 0..27 ----
            float memv = 0.f;
            if (lane < 28) {
                float t     = xf - muv;
                float gauss = __expf(-t * t * i2s);
                float left  = fminf(fmaxf((xf - av) * iba, 0.f), 1.f);
                float right = fminf(fmaxf((dv - xf) * idc, 0.f), 1.f);
                float flat  = (xf >= bv && xf <= cv) ? 1.f : 0.f;
                float trap  = fmaxf(fminf(left, right), flat);
                memv = trap + alpha * (gauss - trap);
                __stcs(outM + b0 * 14 + lane, memv);
            }

            // ---- gathers: element A (lanes 0..13), element B (+14) ----
            float a_g0 = __shfl_sync(FULL_MASK, memv, src0);
            float b_g0 = __shfl_sync(FULL_MASK, memv, src0 + 14);
            float a_g1 = __shfl_sync(FULL_MASK, memv, src1);
            float b_g1 = __shfl_sync(FULL_MASK, memv, src1 + 14);
            float a_g2 = __shfl_sync(FULL_MASK, memv, src2);
            float b_g2 = __shfl_sync(FULL_MASK, memv, src2 + 14);
            float a_g3 = __shfl_sync(FULL_MASK, memv, src3);
            float b_g3 = __shfl_sync(FULL_MASK, memv, src3 + 14);
            float a_g4 = __shfl_sync(FULL_MASK, memv, src4);
            float b_g4 = __shfl_sync(FULL_MASK, memv, src4 + 14);
            // pair features 5 (lanes 10/11) and 6 (lanes 12/13)
            float aA5 = __shfl_sync(FULL_MASK, memv, 10);
            float aB5 = __shfl_sync(FULL_MASK, memv, 11);
            float aA6 = __shfl_sync(FULL_MASK, memv, 12);
            float aB6 = __shfl_sync(FULL_MASK, memv, 13);
            float bA5 = __shfl_sync(FULL_MASK, memv, 24);
            float bB5 = __shfl_sync(FULL_MASK, memv, 25);
            float bA6 = __shfl_sync(FULL_MASK, memv, 26);
            float bB6 = __shfl_sync(FULL_MASK, memv, 27);

            float a_pp = ((a_g0 * a_g1) * (a_g2 * a_g3)) * a_g4;
            float a_pm = fminf(fminf(fminf(a_g0, a_g1), fminf(a_g2, a_g3)), a_g4);
            float b_pp = ((b_g0 * b_g1) * (b_g2 * b_g3)) * b_g4;
            float b_pm = fminf(fminf(fminf(b_g0, b_g1), fminf(b_g2, b_g3)), b_g4);

            float firA[4], firB[4];
            float s1a = 0.f, s2a = 0.f, s1b = 0.f, s2b = 0.f;
#pragma unroll
            for (int k = 0; k < 4; ++k) {
                // coefficients from SMEM: conflict-free LDS.128
                const float4 c0 = sC[k][0][lane];
                const float4 c1 = sC[k][1][lane];

                // compile-time feature-5/6 selection: f5 = bit1(k), f6 = bit0(k)
                float u  = (k & 2) ? aB5 : aA5;
                float v  = (k & 1) ? aB6 : aA6;
                float u2 = (k & 2) ? bB5 : bA5;
                float v2 = (k & 1) ? bB6 : bA6;

                float p   = a_pp * (u * v);
                float mn  = fminf(a_pm, fminf(u, v));
                float fA  = mn + w * (p - mn);
                firA[k] = fA;
                float p2  = b_pp * (u2 * v2);
                float mn2 = fminf(b_pm, fminf(u2, v2));
                float fB  = mn2 + w * (p2 - mn2);
                firB[k] = fB;

                float roA = c0.x;
                roA = fmaf(c0.y, ax0, roA);
                roA = fmaf(c0.z, ax1, roA);
                roA = fmaf(c0.w, ax2, roA);
                roA = fmaf(c1.x, ax3, roA);
                roA = fmaf(c1.y, ax4, roA);
                roA = fmaf(c1.z, ax5, roA);
                roA = fmaf(c1.w, ax6, roA);
                float roB = c0.x;
                roB = fmaf(c0.y, bx0, roB);
                roB = fmaf(c0.z, bx1, roB);
                roB = fmaf(c0.w, bx2, roB);
                roB = fmaf(c1.x, bx3, roB);
                roB = fmaf(c1.y, bx4, roB);
                roB = fmaf(c1.z, bx5, roB);
                roB = fmaf(c1.w, bx6, roB);

                s1a += fA; s2a = fmaf(fA, roA, s2a);
                s1b += fB; s2b = fmaf(fB, roB, s2b);
            }

            // ---- 4 interleaved butterfly reduction chains ----
#pragma unroll
            for (int off = 16; off > 0; off >>= 1) {
                s1a += __shfl_xor_sync(FULL_MASK, s1a, off);
                s1b += __shfl_xor_sync(FULL_MASK, s1b, off);
                s2a += __shfl_xor_sync(FULL_MASK, s2a, off);
                s2b += __shfl_xor_sync(FULL_MASK, s2b, off);
            }
            const float invA = __fdividef(1.f, s1a + 1e-8f);
            const float invB = __fdividef(1.f, s1b + 1e-8f);

            float4 nfA = make_float4(firA[0]*invA, firA[1]*invA, firA[2]*invA, firA[3]*invA);
            float4 nfB = make_float4(firB[0]*invB, firB[1]*invB, firB[2]*invB, firB[3]*invB);
            __stcs(reinterpret_cast<float4*>(outN + b0 * 128) + lane, nfA);
            __stcs(reinterpret_cast<float4*>(outN + (b0 + 1) * 128) + lane, nfB);
            if (lane == 0) {
                // out0 + b0 is 8B-aligned (b0 even): one packed STG.64
                float2 o2 = make_float2(s2a * invA, s2b * invB);
                __stcs(reinterpret_cast<float2*>(out0 + b0), o2);
            }

            xf = xf_next;
        }
    } else {
        // ---- generic fallback (structure violated or odd B): 1 element/iter ----
        for (int b = warp; b < B; b += nwarps) {
            const float* xb = x + b * 7;
            float xv0 = __ldg(xb+0), xv1 = __ldg(xb+1), xv2 = __ldg(xb+2),
                  xv3 = __ldg(xb+3), xv4 = __ldg(xb+4), xv5 = __ldg(xb+5),
                  xv6 = __ldg(xb+6);
            float memv = 0.f;
            if (lane < 14) {
                float xfv = __ldg(xb + (lane >> 1));
                float t     = xfv - muv;
                float gauss = __expf(-t * t * i2s);
                float left  = fminf(fmaxf((xfv - av) * iba, 0.f), 1.f);
                float right = fminf(fmaxf((dv - xfv) * idc, 0.f), 1.f);
                float flat  = (xfv >= bv && xfv <= cv) ? 1.f : 0.f;
                float trap  = fmaxf(fminf(left, right), flat);
                memv = trap + alpha * (gauss - trap);
                outM[b * 14 + lane] = memv;
            }
            float mA[7], mB[7];
#pragma unroll
            for (int f = 0; f < 7; ++f) {
                mA[f] = __shfl_sync(FULL_MASK, memv, 2 * f);
                mB[f] = __shfl_sync(FULL_MASK, memv, 2 * f + 1);
            }
            float fir[4], s1 = 0.f, s2 = 0.f;
#pragma unroll
            for (int k = 0; k < 4; ++k) {
                const int m = mask[k];
                const float4 c0 = sC[k][0][lane];
                const float4 c1 = sC[k][1][lane];
                float p = 1.f, mn = 2.f;
#pragma unroll
                for (int f = 0; f < 7; ++f) {
                    float g = (m & (1 << f)) ? mB[f] : mA[f];
                    p *= g; mn = fminf(mn, g);
                }
                float fk = mn + w * (p - mn);
                fir[k] = fk;
                float ro = c0.x;
                ro = fmaf(c0.y, xv0, ro);
                ro = fmaf(c0.z, xv1, ro);
                ro = fmaf(c0.w, xv2, ro);
                ro = fmaf(c1.x, xv3, ro);
                ro = fmaf(c1.y, xv4, ro);
                ro = fmaf(c1.z, xv5, ro);
                ro = fmaf(c1.w, xv6, ro);
                s1 += fk;
                s2 = fmaf(fk, ro, s2);
            }
#pragma unroll
            for (int off = 16; off > 0; off >>= 1) {
                s1 += __shfl_xor_sync(FULL_MASK, s1, off);
                s2 += __shfl_xor_sync(FULL_MASK, s2, off);
            }
            const float inv = __fdividef(1.f, s1 + 1e-8f);
            float4 nf = make_float4(fir[0]*inv, fir[1]*inv, fir[2]*inv, fir[3]*inv);
            reinterpret_cast<float4*>(outN + b * 128)[lane] = nf;
            if (lane == 0) out0[b] = s2 * inv;
        }
    }
}

extern "C" void kernel_launch(void* const* d_in, const int* in_sizes, int n_in,
                              void* d_out, int out_size) {
    const float* x      = (const float*)d_in[0];
    const float* mu     = (const float*)d_in[1];
    const float* sg     = (const float*)d_in[2];
    const float* ta     = (const float*)d_in[3];
    const float* tb     = (const float*)d_in[4];
    const float* tc     = (const float*)d_in[5];
    const float* td     = (const float*)d_in[6];
    const float* mfmix  = (const float*)d_in[7];
    const float* tnw    = (const float*)d_in[8];
    const float* conseq = (const float*)d_in[9];
    const int*   ridx   = (const int*)d_in[10];

    const int B = in_sizes[0] / 7;

    float* o  = (float*)d_out;
    float* oN = o + B;                // norm_firing [B,128]
    float* oM = o + B + B * 128;      // mem [B,14]

    // Single wave: 148 SMs x 7 blocks/SM, 128 threads (28 warps/SM), 2 elem/warp-iter
    anfis_kernel<<<1036, 128>>>(x, mu, sg, ta, tb, tc, td, mfmix, tnw,
                                conseq, ridx, o, oN, oM, B);
}